// round 8
// baseline (speedup 1.0000x reference)
#include <cuda_runtime.h>
#include <cuda_bf16.h>
#include <cuda_fp16.h>
#include <stdint.h>

// Problem constants
#define NN 10000          // nodes
#define EE 160000         // edges
#define DD 512            // feature dim (in == out)
#define DV8 (DD/8)        // 64 uint4-of-half per row

// ---------------- device scratch (no allocs allowed) ----------------
__device__ float g_dinv[NN];
__device__ int   g_counts[NN];
__device__ int   g_offsets[NN + 1];
__device__ int   g_cursor[NN];
__device__ int   g_esrc[EE];                      // per-slot source node
__device__ float g_enorm[EE];                     // per-slot norm coeff
__device__ __half g_h[(size_t)NN * DD];           // h = x @ W (fp16, 10.2 MB)
__device__ __nv_bfloat16 g_xh[(size_t)NN * DD];   // x hi split
__device__ __nv_bfloat16 g_xl[(size_t)NN * DD];   // x lo split
__device__ __nv_bfloat16 g_wth[(size_t)DD * DD];  // W^T hi: [n][k]
__device__ __nv_bfloat16 g_wtl[(size_t)DD * DD];  // W^T lo

// =================== helpers ===================
__device__ __forceinline__ uint32_t smem_to_u32(const void* p) {
    uint32_t a;
    asm("{ .reg .u64 t; cvta.to.shared.u64 t, %1; cvt.u32.u64 %0, t; }"
        : "=r"(a) : "l"(p));
    return a;
}
// XOR swizzle for 64B rows
#define SWZ64(o) ((o) ^ (((o) >> 3) & 0x30))

__device__ __forceinline__ void ldsm_x4(uint32_t r[4], uint32_t addr) {
    asm volatile("ldmatrix.sync.aligned.m8n8.x4.shared.b16 {%0,%1,%2,%3}, [%4];"
                 : "=r"(r[0]), "=r"(r[1]), "=r"(r[2]), "=r"(r[3]) : "r"(addr));
}
__device__ __forceinline__ void mma16816(float c[4], const uint32_t a[4],
                                         uint32_t b0, uint32_t b1) {
    asm volatile(
        "mma.sync.aligned.m16n8k16.row.col.f32.bf16.bf16.f32 "
        "{%0,%1,%2,%3}, {%4,%5,%6,%7}, {%8,%9}, {%0,%1,%2,%3};"
        : "+f"(c[0]), "+f"(c[1]), "+f"(c[2]), "+f"(c[3])
        : "r"(a[0]), "r"(a[1]), "r"(a[2]), "r"(a[3]), "r"(b0), "r"(b1));
}
__device__ __forceinline__ void cp16(uint32_t dst, const void* src) {
    asm volatile("cp.async.cg.shared.global [%0], [%1], 16;"
                 :: "r"(dst), "l"(src));
}
#define CP_COMMIT() asm volatile("cp.async.commit_group;" ::: "memory")
#define CP_WAIT1()  asm volatile("cp.async.wait_group 1;" ::: "memory")
#define CP_WAIT0()  asm volatile("cp.async.wait_group 0;" ::: "memory")

// =================== prep: split x + transpose/split W ===================
// blocks [0,5000): x split; [5000,5512): W cols
__global__ void prep_kernel(const float* __restrict__ x,
                            const float* __restrict__ W) {
    const int bid = blockIdx.x;
    if (bid < 5000) {
        size_t i = (size_t)bid * 256 + threadIdx.x;   // float4 index
        float4 v = ((const float4*)x)[i];
        __nv_bfloat16 h0 = __float2bfloat16(v.x);
        __nv_bfloat16 h1 = __float2bfloat16(v.y);
        __nv_bfloat16 h2 = __float2bfloat16(v.z);
        __nv_bfloat16 h3 = __float2bfloat16(v.w);
        __nv_bfloat16 l0 = __float2bfloat16(v.x - __bfloat162float(h0));
        __nv_bfloat16 l1 = __float2bfloat16(v.y - __bfloat162float(h1));
        __nv_bfloat16 l2 = __float2bfloat16(v.z - __bfloat162float(h2));
        __nv_bfloat16 l3 = __float2bfloat16(v.w - __bfloat162float(h3));
        __nv_bfloat162 ph0 = __halves2bfloat162(h0, h1);
        __nv_bfloat162 ph1 = __halves2bfloat162(h2, h3);
        __nv_bfloat162 pl0 = __halves2bfloat162(l0, l1);
        __nv_bfloat162 pl1 = __halves2bfloat162(l2, l3);
        uint2 ph, pl;
        ph.x = *(uint32_t*)&ph0; ph.y = *(uint32_t*)&ph1;
        pl.x = *(uint32_t*)&pl0; pl.y = *(uint32_t*)&pl1;
        ((uint2*)g_xh)[i] = ph;
        ((uint2*)g_xl)[i] = pl;
    } else {
        int n = bid - 5000;
        for (int k = threadIdx.x; k < DD; k += 256) {
            float v = W[(size_t)k * DD + n];
            __nv_bfloat16 h = __float2bfloat16(v);
            __nv_bfloat16 l = __float2bfloat16(v - __bfloat162float(h));
            g_wth[(size_t)n * DD + k] = h;
            g_wtl[(size_t)n * DD + k] = l;
        }
    }
}

// =================== CSR-build kernels (stream 2) ===================
__global__ void init_kernel() {
    int i = blockIdx.x * blockDim.x + threadIdx.x;
    if (i < NN) { g_dinv[i] = 1.0f; g_counts[i] = 0; }
}

__global__ void deg_kernel(const int* __restrict__ eidx,
                           const float* __restrict__ ew) {
    int e = blockIdx.x * blockDim.x + threadIdx.x;
    if (e < EE) {
        int c = eidx[EE + e];
        atomicAdd(&g_dinv[c], ew[e]);
        atomicAdd(&g_counts[c], 1);
    }
}

// scan (warp-shuffle) + dinv finalize, 1 block of 1024
__global__ void scan_kernel() {
    __shared__ int warpsum[32];
    const int CH = (NN + 1023) / 1024;   // 10
    int t = threadIdx.x;
    int lane = t & 31, w = t >> 5;
    int base = t * CH;
    int local[CH];
    int sum = 0;
#pragma unroll
    for (int i = 0; i < CH; ++i) {
        int idx = base + i;
        local[i] = (idx < NN) ? g_counts[idx] : 0;
        sum += local[i];
        if (idx < NN) g_dinv[idx] = rsqrtf(g_dinv[idx]);
    }
    int v = sum;
#pragma unroll
    for (int o = 1; o < 32; o <<= 1) {
        int u = __shfl_up_sync(0xFFFFFFFFu, v, o);
        if (lane >= o) v += u;
    }
    if (lane == 31) warpsum[w] = v;
    __syncthreads();
    if (w == 0) {
        int s = warpsum[lane];
#pragma unroll
        for (int o = 1; o < 32; o <<= 1) {
            int u = __shfl_up_sync(0xFFFFFFFFu, s, o);
            if (lane >= o) s += u;
        }
        warpsum[lane] = s;
    }
    __syncthreads();
    int run = v - sum + (w ? warpsum[w - 1] : 0);
#pragma unroll
    for (int i = 0; i < CH; ++i) {
        int idx = base + i;
        if (idx < NN) {
            g_offsets[idx] = run;
            g_cursor[idx]  = run;
            run += local[i];
        }
    }
    if (t == 1023) g_offsets[NN] = warpsum[31];
}

// fill: resolve (src, norm) per slot (dinv is final here)
__global__ void fill_kernel(const int* __restrict__ eidx,
                            const float* __restrict__ ew) {
    int e = blockIdx.x * blockDim.x + threadIdx.x;
    if (e < EE) {
        int c = eidx[EE + e];
        int r = eidx[e];
        float nrm = g_dinv[r] * ew[e] * g_dinv[c];
        int p = atomicAdd(&g_cursor[c], 1);
        g_esrc[p]  = r;
        g_enorm[p] = nrm;
    }
}

// =================== mma.sync GEMM: g_h = x @ W (fp16 out) ===================
// CTA tile 128(M) x 128(N), K-chunk 32, 2-stage cp.async pipeline.
// nHalf selects N columns [nHalf*256, nHalf*256+256). Grid (2, 79).
// Stage layout (32KB): A_HI 0 | A_LO 8K | B_HI 16K | B_LO 24K ; 64B rows, SW64.
#define KC 32
#define NCH (DD / KC)            // 16
#define STAGE 32768
#define GEMM_SMEM (2 * STAGE)    // 65536

__device__ __forceinline__ void gemm_load_stage(uint32_t sb, int stOff, int kc,
                                                int tid, int mBase, int nBase) {
    const int kOff = kc * KC;
#pragma unroll
    for (int it = 0; it < 8; ++it) {
        int vv = tid + it * 256;            // 0..2047
        int row = (vv & 511) >> 2;          // 0..127
        int g   = vv & 3;                   // 16B unit
        const __nv_bfloat16* srcp;
        int region;
        size_t srcRow;
        if (vv < 1024) {
            int m = mBase + row; if (m > NN - 1) m = NN - 1;
            srcp = (vv < 512) ? g_xh : g_xl;
            region = (vv < 512) ? 0 : 8192;
            srcRow = (size_t)m;
        } else {
            srcp = (vv < 1536) ? g_wth : g_wtl;
            region = (vv < 1536) ? 16384 : 24576;
            srcRow = (size_t)(nBase + row);
        }
        cp16(sb + stOff + region + SWZ64(row * 64 + g * 16),
             srcp + srcRow * DD + kOff + g * 8);
    }
}

__global__ void __launch_bounds__(256, 2)
gemm_kernel(int nHalf) {
    extern __shared__ char smem[];
    const uint32_t sb = smem_to_u32(smem);
    const int tid  = threadIdx.x;
    const int wid  = tid >> 5;
    const int lane = tid & 31;
    const int wy   = wid >> 2;            // 0..1  (M)
    const int wx   = wid & 3;             // 0..3  (N)
    const int mBase = blockIdx.y * 128;
    const int nBase = nHalf * 256 + blockIdx.x * 128;

    float c[4][4][4];
#pragma unroll
    for (int i = 0; i < 4; ++i)
#pragma unroll
        for (int j = 0; j < 4; ++j)
#pragma unroll
            for (int r = 0; r < 4; ++r) c[i][j][r] = 0.0f;

    const int aRow = wy * 64 + (lane & 15);
    const int aKu  = (lane >> 4);
    const int bRow = wx * 32 + (lane & 7) + ((lane >> 4) & 1) * 8;
    const int bKu  = ((lane >> 3) & 1);

    gemm_load_stage(sb, 0, 0, tid, mBase, nBase);
    CP_COMMIT();

    for (int kc = 0; kc < NCH; ++kc) {
        const int stOff = (kc & 1) * STAGE;
        if (kc + 1 < NCH) {
            gemm_load_stage(sb, ((kc + 1) & 1) * STAGE, kc + 1, tid, mBase, nBase);
            CP_COMMIT();
            CP_WAIT1();
        } else {
            CP_WAIT0();
        }
        __syncthreads();

#pragma unroll
        for (int k16 = 0; k16 < 2; ++k16) {
            const int kb = k16 * 2;
            uint32_t a[4][4], bh[2][4], bl[2][4];
#pragma unroll
            for (int mt = 0; mt < 4; ++mt) {
                int off = SWZ64((aRow + mt * 16) * 64 + (kb + aKu) * 16);
                ldsm_x4(a[mt], sb + stOff + 0 + off);
            }
#pragma unroll
            for (int pr = 0; pr < 2; ++pr) {
                int off = SWZ64((bRow + pr * 16) * 64 + (kb + bKu) * 16);
                ldsm_x4(bh[pr], sb + stOff + 16384 + off);
                ldsm_x4(bl[pr], sb + stOff + 24576 + off);
            }
            // hi*hi
#pragma unroll
            for (int mt = 0; mt < 4; ++mt)
#pragma unroll
                for (int nt = 0; nt < 4; ++nt)
                    mma16816(c[mt][nt], a[mt], bh[nt >> 1][(nt & 1) * 2],
                             bh[nt >> 1][(nt & 1) * 2 + 1]);
            // hi*lo
#pragma unroll
            for (int mt = 0; mt < 4; ++mt)
#pragma unroll
                for (int nt = 0; nt < 4; ++nt)
                    mma16816(c[mt][nt], a[mt], bl[nt >> 1][(nt & 1) * 2],
                             bl[nt >> 1][(nt & 1) * 2 + 1]);
            // lo*hi
#pragma unroll
            for (int mt = 0; mt < 4; ++mt) {
                int off = SWZ64((aRow + mt * 16) * 64 + (kb + aKu) * 16);
                ldsm_x4(a[mt], sb + stOff + 8192 + off);
            }
#pragma unroll
            for (int mt = 0; mt < 4; ++mt)
#pragma unroll
                for (int nt = 0; nt < 4; ++nt)
                    mma16816(c[mt][nt], a[mt], bh[nt >> 1][(nt & 1) * 2],
                             bh[nt >> 1][(nt & 1) * 2 + 1]);
        }
        __syncthreads();
    }

    // epilogue: half2 stores to g_h
    const int erow = mBase + wy * 64 + (lane >> 2);
    const int ecol = nBase + wx * 32 + (lane & 3) * 2;
#pragma unroll
    for (int mt = 0; mt < 4; ++mt) {
#pragma unroll
        for (int nt = 0; nt < 4; ++nt) {
            int r0 = erow + mt * 16;
            int cc = ecol + nt * 8;
            if (r0 < NN) {
                __half2 p = __floats2half2_rn(c[mt][nt][0], c[mt][nt][1]);
                *(__half2*)&g_h[(size_t)r0 * DD + cc] = p;
            }
            if (r0 + 8 < NN) {
                __half2 p = __floats2half2_rn(c[mt][nt][2], c[mt][nt][3]);
                *(__half2*)&g_h[(size_t)(r0 + 8) * DD + cc] = p;
            }
        }
    }
}

// =================== aggregation (fp16 rows, N-half, 32 thr/node) ===================
__device__ __forceinline__ void fma_h8(float acc[8], uint4 v, float n) {
    __half2* hp = (__half2*)&v;
#pragma unroll
    for (int q = 0; q < 4; ++q) {
        float2 f = __half22float2(hp[q]);
        acc[q * 2 + 0] += f.x * n;
        acc[q * 2 + 1] += f.y * n;
    }
}

// colOff: uint4-unit column offset (0 for left half, 32 for right half)
__global__ __launch_bounds__(32)
void agg_kernel(const float* __restrict__ bias,
                float* __restrict__ out, int colOff) {
    const int i = blockIdx.x;
    const int t = threadIdx.x + colOff;   // uint4 index within row (owns 8 cols)
    const uint4* hb = (const uint4*)g_h;

    const float di = g_dinv[i];
    float acc[8];
    {
        const float4* bp = (const float4*)(bias + t * 8);
        float4 b0 = bp[0], b1 = bp[1];
        acc[0] = b0.x; acc[1] = b0.y; acc[2] = b0.z; acc[3] = b0.w;
        acc[4] = b1.x; acc[5] = b1.y; acc[6] = b1.z; acc[7] = b1.w;
    }
    // self loop
    fma_h8(acc, hb[(size_t)i * DV8 + t], di * di);

    int k = g_offsets[i];
    const int kend = g_offsets[i + 1];
    for (; k + 3 < kend; k += 4) {
        int r0 = g_esrc[k],     r1 = g_esrc[k + 1];
        int r2 = g_esrc[k + 2], r3 = g_esrc[k + 3];
        float n0 = g_enorm[k],     n1 = g_enorm[k + 1];
        float n2 = g_enorm[k + 2], n3 = g_enorm[k + 3];
        uint4 v0 = hb[(size_t)r0 * DV8 + t];
        uint4 v1 = hb[(size_t)r1 * DV8 + t];
        uint4 v2 = hb[(size_t)r2 * DV8 + t];
        uint4 v3 = hb[(size_t)r3 * DV8 + t];
        fma_h8(acc, v0, n0);
        fma_h8(acc, v1, n1);
        fma_h8(acc, v2, n2);
        fma_h8(acc, v3, n3);
    }
    for (; k < kend; ++k)
        fma_h8(acc, hb[(size_t)g_esrc[k] * DV8 + t], g_enorm[k]);

    float4* op = (float4*)(out + (size_t)i * DD + t * 8);
    op[0] = make_float4(acc[0], acc[1], acc[2], acc[3]);
    op[1] = make_float4(acc[4], acc[5], acc[6], acc[7]);
}

// =================== launcher: GEMM/agg N-half pipeline + CSR fork ===================
extern "C" void kernel_launch(void* const* d_in, const int* in_sizes, int n_in,
                              void* d_out, int out_size) {
    const float* x    = (const float*)d_in[0];       // [NN, DD]
    const int*   eidx = (const int*)d_in[1];         // [2, EE] int32
    const float* ea   = (const float*)d_in[2];       // [EE]
    const float* W    = (const float*)d_in[3];       // [DD, DD]
    const float* b    = (const float*)d_in[4];       // [DD]
    float*       out  = (float*)d_out;               // [NN, DD]

    static cudaStream_t s2 = nullptr;
    static cudaEvent_t evFork = nullptr, evJoin = nullptr, evGL = nullptr;
    if (s2 == nullptr) {
        cudaStreamCreateWithFlags(&s2, cudaStreamNonBlocking);
        cudaEventCreateWithFlags(&evFork, cudaEventDisableTiming);
        cudaEventCreateWithFlags(&evJoin, cudaEventDisableTiming);
        cudaEventCreateWithFlags(&evGL, cudaEventDisableTiming);
        cudaFuncSetAttribute(gemm_kernel,
                             cudaFuncAttributeMaxDynamicSharedMemorySize, GEMM_SMEM);
    }

    // fork CSR chain onto s2 immediately
    cudaEventRecord(evFork, 0);
    cudaStreamWaitEvent(s2, evFork, 0);
    init_kernel<<<(NN + 255) / 256, 256, 0, s2>>>();
    deg_kernel<<<(EE + 255) / 256, 256, 0, s2>>>(eidx, ea);
    scan_kernel<<<1, 1024, 0, s2>>>();
    fill_kernel<<<(EE + 255) / 256, 256, 0, s2>>>(eidx, ea);
    // s2 now holds completed CSR state

    // main stream: prep then left-half GEMM
    prep_kernel<<<5512, 256>>>(x, W);
    dim3 ghalf(2, (NN + 127) / 128);                 // (2, 79)
    gemm_kernel<<<ghalf, 256, GEMM_SMEM>>>(0);
    cudaEventRecord(evGL, 0);

    // right-half GEMM on main stream; left-half agg on s2 (overlaps gemm_R)
    cudaStreamWaitEvent(s2, evGL, 0);
    agg_kernel<<<NN, 32, 0, s2>>>(b, out, 0);
    cudaEventRecord(evJoin, s2);

    gemm_kernel<<<ghalf, 256, GEMM_SMEM>>>(1);
    agg_kernel<<<NN, 32>>>(b, out, 32);

    // ensure left-half agg complete before stream-0 "done"
    cudaStreamWaitEvent(0, evJoin, 0);
}

// round 9
// speedup vs baseline: 1.3464x; 1.3464x over previous
#include <cuda_runtime.h>
#include <cuda_bf16.h>
#include <cuda_fp16.h>
#include <stdint.h>

// Problem constants
#define NN 10000          // nodes
#define EE 160000         // edges
#define DD 512            // feature dim (in == out)
#define DV8 (DD/8)        // 64 uint4-of-half per row

// ---------------- device scratch (no allocs allowed) ----------------
__device__ float g_dinv[NN];
__device__ int   g_counts[NN];
__device__ int   g_offsets[NN + 1];
__device__ int   g_cursor[NN];
__device__ int   g_esrc[EE];                      // per-slot source node
__device__ float g_enorm[EE];                     // per-slot norm coeff
__device__ __half g_h[(size_t)NN * DD];           // h = x @ W (fp16, 10.2 MB)
__device__ __half g_x16[(size_t)NN * DD];         // x in fp16 (10.2 MB)
__device__ __half g_wth[(size_t)DD * DD];         // W^T hi: [n][k] fp16
__device__ __half g_wtl[(size_t)DD * DD];         // W^T lo: residual fp16

// =================== helpers ===================
__device__ __forceinline__ uint32_t smem_to_u32(const void* p) {
    uint32_t a;
    asm("{ .reg .u64 t; cvta.to.shared.u64 t, %1; cvt.u32.u64 %0, t; }"
        : "=r"(a) : "l"(p));
    return a;
}
// XOR swizzle for 64B rows
#define SWZ64(o) ((o) ^ (((o) >> 3) & 0x30))

__device__ __forceinline__ void ldsm_x4(uint32_t r[4], uint32_t addr) {
    asm volatile("ldmatrix.sync.aligned.m8n8.x4.shared.b16 {%0,%1,%2,%3}, [%4];"
                 : "=r"(r[0]), "=r"(r[1]), "=r"(r[2]), "=r"(r[3]) : "r"(addr));
}
__device__ __forceinline__ void mma16816(float c[4], const uint32_t a[4],
                                         uint32_t b0, uint32_t b1) {
    asm volatile(
        "mma.sync.aligned.m16n8k16.row.col.f32.f16.f16.f32 "
        "{%0,%1,%2,%3}, {%4,%5,%6,%7}, {%8,%9}, {%0,%1,%2,%3};"
        : "+f"(c[0]), "+f"(c[1]), "+f"(c[2]), "+f"(c[3])
        : "r"(a[0]), "r"(a[1]), "r"(a[2]), "r"(a[3]), "r"(b0), "r"(b1));
}
__device__ __forceinline__ void cp16(uint32_t dst, const void* src) {
    asm volatile("cp.async.cg.shared.global [%0], [%1], 16;"
                 :: "r"(dst), "l"(src));
}
#define CP_COMMIT() asm volatile("cp.async.commit_group;" ::: "memory")
#define CP_WAIT1()  asm volatile("cp.async.wait_group 1;" ::: "memory")
#define CP_WAIT0()  asm volatile("cp.async.wait_group 0;" ::: "memory")

// =================== prep: x -> fp16; W -> transposed hi/lo fp16 ===================
// blocks [0,2500): x convert (float4 -> 4 halves); [2500,3012): W cols
__global__ void prep_kernel(const float* __restrict__ x,
                            const float* __restrict__ W) {
    const int bid = blockIdx.x;
    if (bid < 2500) {
        size_t i = (size_t)bid * 512 + threadIdx.x * 2;   // float4 index (2 per thread)
        const float4* xp = (const float4*)x;
#pragma unroll
        for (int q = 0; q < 2; ++q) {
            float4 v = xp[i + q];
            __half2 p0 = __floats2half2_rn(v.x, v.y);
            __half2 p1 = __floats2half2_rn(v.z, v.w);
            uint2 pk;
            pk.x = *(uint32_t*)&p0; pk.y = *(uint32_t*)&p1;
            ((uint2*)g_x16)[i + q] = pk;
        }
    } else {
        int n = bid - 2500;
        for (int k = threadIdx.x; k < DD; k += 256) {
            float v = W[(size_t)k * DD + n];
            __half h = __float2half_rn(v);
            __half l = __float2half_rn(v - __half2float(h));
            g_wth[(size_t)n * DD + k] = h;
            g_wtl[(size_t)n * DD + k] = l;
        }
    }
}

// =================== CSR-build kernels (stream 2) ===================
__global__ void init_kernel() {
    int i = blockIdx.x * blockDim.x + threadIdx.x;
    if (i < NN) { g_dinv[i] = 1.0f; g_counts[i] = 0; }
}

__global__ void deg_kernel(const int* __restrict__ eidx,
                           const float* __restrict__ ew) {
    int e = blockIdx.x * blockDim.x + threadIdx.x;
    if (e < EE) {
        int c = eidx[EE + e];
        atomicAdd(&g_dinv[c], ew[e]);
        atomicAdd(&g_counts[c], 1);
    }
}

// scan (warp-shuffle) + dinv finalize, 1 block of 1024
__global__ void scan_kernel() {
    __shared__ int warpsum[32];
    const int CH = (NN + 1023) / 1024;   // 10
    int t = threadIdx.x;
    int lane = t & 31, w = t >> 5;
    int base = t * CH;
    int local[CH];
    int sum = 0;
#pragma unroll
    for (int i = 0; i < CH; ++i) {
        int idx = base + i;
        local[i] = (idx < NN) ? g_counts[idx] : 0;
        sum += local[i];
        if (idx < NN) g_dinv[idx] = rsqrtf(g_dinv[idx]);
    }
    int v = sum;
#pragma unroll
    for (int o = 1; o < 32; o <<= 1) {
        int u = __shfl_up_sync(0xFFFFFFFFu, v, o);
        if (lane >= o) v += u;
    }
    if (lane == 31) warpsum[w] = v;
    __syncthreads();
    if (w == 0) {
        int s = warpsum[lane];
#pragma unroll
        for (int o = 1; o < 32; o <<= 1) {
            int u = __shfl_up_sync(0xFFFFFFFFu, s, o);
            if (lane >= o) s += u;
        }
        warpsum[lane] = s;
    }
    __syncthreads();
    int run = v - sum + (w ? warpsum[w - 1] : 0);
#pragma unroll
    for (int i = 0; i < CH; ++i) {
        int idx = base + i;
        if (idx < NN) {
            g_offsets[idx] = run;
            g_cursor[idx]  = run;
            run += local[i];
        }
    }
    if (t == 1023) g_offsets[NN] = warpsum[31];
}

// fill: resolve (src, norm) per slot (dinv is final here)
__global__ void fill_kernel(const int* __restrict__ eidx,
                            const float* __restrict__ ew) {
    int e = blockIdx.x * blockDim.x + threadIdx.x;
    if (e < EE) {
        int c = eidx[EE + e];
        int r = eidx[e];
        float nrm = g_dinv[r] * ew[e] * g_dinv[c];
        int p = atomicAdd(&g_cursor[c], 1);
        g_esrc[p]  = r;
        g_enorm[p] = nrm;
    }
}

// =================== mma.sync fp16 GEMM: g_h = x16 @ (Wh + Wl) ===================
// CTA tile 128(M) x 128(N), K-chunk 32, 2-stage cp.async pipeline.
// Stage layout (24KB): A 0 | B_HI 8K | B_LO 16K ; 64B rows, SW64.
#define KC 32
#define NCH (DD / KC)            // 16
#define STAGE 24576
#define GEMM_SMEM (2 * STAGE)    // 49152

__device__ __forceinline__ void gemm_load_stage(uint32_t sb, int stOff, int kc,
                                                int tid, int mBase, int nBase) {
    const int kOff = kc * KC;
#pragma unroll
    for (int it = 0; it < 6; ++it) {
        int vv = tid + it * 256;            // 0..1535
        int row = (vv & 511) >> 2;          // 0..127
        int g   = vv & 3;                   // 16B unit
        const __half* srcp;
        int region;
        size_t srcRow;
        if (vv < 512) {
            int m = mBase + row; if (m > NN - 1) m = NN - 1;
            srcp = g_x16;
            region = 0;
            srcRow = (size_t)m;
        } else {
            srcp = (vv < 1024) ? g_wth : g_wtl;
            region = (vv < 1024) ? 8192 : 16384;
            srcRow = (size_t)(nBase + row);
        }
        cp16(sb + stOff + region + SWZ64(row * 64 + g * 16),
             srcp + srcRow * DD + kOff + g * 8);
    }
}

__global__ void __launch_bounds__(256, 2)
gemm_kernel() {
    extern __shared__ char smem[];
    const uint32_t sb = smem_to_u32(smem);
    const int tid  = threadIdx.x;
    const int wid  = tid >> 5;
    const int lane = tid & 31;
    const int wy   = wid >> 2;            // 0..1  (M)
    const int wx   = wid & 3;             // 0..3  (N)
    const int mBase = blockIdx.y * 128;
    const int nBase = blockIdx.x * 128;

    float c[4][4][4];
#pragma unroll
    for (int i = 0; i < 4; ++i)
#pragma unroll
        for (int j = 0; j < 4; ++j)
#pragma unroll
            for (int r = 0; r < 4; ++r) c[i][j][r] = 0.0f;

    const int aRow = wy * 64 + (lane & 15);
    const int aKu  = (lane >> 4);
    const int bRow = wx * 32 + (lane & 7) + ((lane >> 4) & 1) * 8;
    const int bKu  = ((lane >> 3) & 1);

    gemm_load_stage(sb, 0, 0, tid, mBase, nBase);
    CP_COMMIT();

    for (int kc = 0; kc < NCH; ++kc) {
        const int stOff = (kc & 1) * STAGE;
        if (kc + 1 < NCH) {
            gemm_load_stage(sb, ((kc + 1) & 1) * STAGE, kc + 1, tid, mBase, nBase);
            CP_COMMIT();
            CP_WAIT1();
        } else {
            CP_WAIT0();
        }
        __syncthreads();

#pragma unroll
        for (int k16 = 0; k16 < 2; ++k16) {
            const int kb = k16 * 2;
            uint32_t a[4][4], bh[2][4], bl[2][4];
#pragma unroll
            for (int mt = 0; mt < 4; ++mt) {
                int off = SWZ64((aRow + mt * 16) * 64 + (kb + aKu) * 16);
                ldsm_x4(a[mt], sb + stOff + 0 + off);
            }
#pragma unroll
            for (int pr = 0; pr < 2; ++pr) {
                int off = SWZ64((bRow + pr * 16) * 64 + (kb + bKu) * 16);
                ldsm_x4(bh[pr], sb + stOff + 8192 + off);
                ldsm_x4(bl[pr], sb + stOff + 16384 + off);
            }
            // x16 * W_hi
#pragma unroll
            for (int mt = 0; mt < 4; ++mt)
#pragma unroll
                for (int nt = 0; nt < 4; ++nt)
                    mma16816(c[mt][nt], a[mt], bh[nt >> 1][(nt & 1) * 2],
                             bh[nt >> 1][(nt & 1) * 2 + 1]);
            // x16 * W_lo
#pragma unroll
            for (int mt = 0; mt < 4; ++mt)
#pragma unroll
                for (int nt = 0; nt < 4; ++nt)
                    mma16816(c[mt][nt], a[mt], bl[nt >> 1][(nt & 1) * 2],
                             bl[nt >> 1][(nt & 1) * 2 + 1]);
        }
        __syncthreads();
    }

    // epilogue: half2 stores to g_h
    const int erow = mBase + wy * 64 + (lane >> 2);
    const int ecol = nBase + wx * 32 + (lane & 3) * 2;
#pragma unroll
    for (int mt = 0; mt < 4; ++mt) {
#pragma unroll
        for (int nt = 0; nt < 4; ++nt) {
            int r0 = erow + mt * 16;
            int cc = ecol + nt * 8;
            if (r0 < NN) {
                __half2 p = __floats2half2_rn(c[mt][nt][0], c[mt][nt][1]);
                *(__half2*)&g_h[(size_t)r0 * DD + cc] = p;
            }
            if (r0 + 8 < NN) {
                __half2 p = __floats2half2_rn(c[mt][nt][2], c[mt][nt][3]);
                *(__half2*)&g_h[(size_t)(r0 + 8) * DD + cc] = p;
            }
        }
    }
}

// =================== aggregation (fp16 rows, 64 threads/node, unroll 4) ===================
__device__ __forceinline__ void fma_h8(float acc[8], uint4 v, float n) {
    __half2* hp = (__half2*)&v;
#pragma unroll
    for (int q = 0; q < 4; ++q) {
        float2 f = __half22float2(hp[q]);
        acc[q * 2 + 0] += f.x * n;
        acc[q * 2 + 1] += f.y * n;
    }
}

__global__ __launch_bounds__(64)
void agg_kernel(const float* __restrict__ bias,
                float* __restrict__ out) {
    const int i = blockIdx.x;
    const int t = threadIdx.x;          // 0..63, owns 8 columns
    const uint4* hb = (const uint4*)g_h;

    const float di = g_dinv[i];
    float acc[8];
    {
        const float4* bp = (const float4*)(bias + t * 8);
        float4 b0 = bp[0], b1 = bp[1];
        acc[0] = b0.x; acc[1] = b0.y; acc[2] = b0.z; acc[3] = b0.w;
        acc[4] = b1.x; acc[5] = b1.y; acc[6] = b1.z; acc[7] = b1.w;
    }
    // self loop
    fma_h8(acc, hb[(size_t)i * DV8 + t], di * di);

    int k = g_offsets[i];
    const int kend = g_offsets[i + 1];
    for (; k + 3 < kend; k += 4) {
        int r0 = g_esrc[k],     r1 = g_esrc[k + 1];
        int r2 = g_esrc[k + 2], r3 = g_esrc[k + 3];
        float n0 = g_enorm[k],     n1 = g_enorm[k + 1];
        float n2 = g_enorm[k + 2], n3 = g_enorm[k + 3];
        uint4 v0 = hb[(size_t)r0 * DV8 + t];
        uint4 v1 = hb[(size_t)r1 * DV8 + t];
        uint4 v2 = hb[(size_t)r2 * DV8 + t];
        uint4 v3 = hb[(size_t)r3 * DV8 + t];
        fma_h8(acc, v0, n0);
        fma_h8(acc, v1, n1);
        fma_h8(acc, v2, n2);
        fma_h8(acc, v3, n3);
    }
    for (; k < kend; ++k)
        fma_h8(acc, hb[(size_t)g_esrc[k] * DV8 + t], g_enorm[k]);

    float4* op = (float4*)(out + (size_t)i * DD + t * 8);
    op[0] = make_float4(acc[0], acc[1], acc[2], acc[3]);
    op[1] = make_float4(acc[4], acc[5], acc[6], acc[7]);
}

// =================== launcher (fork-join: CSR chain overlaps prep+GEMM) ===================
extern "C" void kernel_launch(void* const* d_in, const int* in_sizes, int n_in,
                              void* d_out, int out_size) {
    const float* x    = (const float*)d_in[0];       // [NN, DD]
    const int*   eidx = (const int*)d_in[1];         // [2, EE] int32
    const float* ea   = (const float*)d_in[2];       // [EE]
    const float* W    = (const float*)d_in[3];       // [DD, DD]
    const float* b    = (const float*)d_in[4];       // [DD]
    float*       out  = (float*)d_out;               // [NN, DD]

    static cudaStream_t s2 = nullptr;
    static cudaEvent_t evFork = nullptr, evJoin = nullptr;
    if (s2 == nullptr) {
        cudaStreamCreateWithFlags(&s2, cudaStreamNonBlocking);
        cudaEventCreateWithFlags(&evFork, cudaEventDisableTiming);
        cudaEventCreateWithFlags(&evJoin, cudaEventDisableTiming);
        cudaFuncSetAttribute(gemm_kernel,
                             cudaFuncAttributeMaxDynamicSharedMemorySize, GEMM_SMEM);
    }

    // fork CSR chain onto s2 immediately
    cudaEventRecord(evFork, 0);
    cudaStreamWaitEvent(s2, evFork, 0);
    init_kernel<<<(NN + 255) / 256, 256, 0, s2>>>();
    deg_kernel<<<(EE + 255) / 256, 256, 0, s2>>>(eidx, ea);
    scan_kernel<<<1, 1024, 0, s2>>>();
    fill_kernel<<<(EE + 255) / 256, 256, 0, s2>>>(eidx, ea);
    cudaEventRecord(evJoin, s2);

    // main stream: prep then GEMM
    prep_kernel<<<3012, 256>>>(x, W);
    dim3 ggrid(DD / 128, (NN + 127) / 128);          // (4, 79)
    gemm_kernel<<<ggrid, 256, GEMM_SMEM>>>();

    // join, then aggregate
    cudaStreamWaitEvent(0, evJoin, 0);
    agg_kernel<<<NN, 64>>>(b, out);
}

// round 10
// speedup vs baseline: 1.7676x; 1.3128x over previous
#include <cuda_runtime.h>
#include <cuda_bf16.h>
#include <cuda_fp16.h>
#include <stdint.h>

// Problem constants
#define NN 10000          // nodes
#define EE 160000         // edges
#define DD 512            // feature dim (in == out)
#define DV8 (DD/8)        // 64 uint4-of-half per row

// ---------------- device scratch (no allocs allowed) ----------------
__device__ float g_dinv[NN];
__device__ int   g_counts[NN];
__device__ int   g_offsets[NN + 1];
__device__ int   g_cursor[NN];
__device__ int   g_esrc[EE];                      // per-slot source node
__device__ float g_enorm[EE];                     // per-slot norm coeff
__device__ __half g_h[(size_t)NN * DD];           // h = x @ W (fp16, 10.2 MB)
__device__ __half g_x16[(size_t)NN * DD];         // x in fp16 (10.2 MB)
__device__ __half g_wt[(size_t)DD * DD];          // W^T: [n][k] fp16

// =================== helpers ===================
__device__ __forceinline__ uint32_t smem_to_u32(const void* p) {
    uint32_t a;
    asm("{ .reg .u64 t; cvta.to.shared.u64 t, %1; cvt.u32.u64 %0, t; }"
        : "=r"(a) : "l"(p));
    return a;
}
// XOR swizzle for 64B rows
#define SWZ64(o) ((o) ^ (((o) >> 3) & 0x30))

__device__ __forceinline__ void ldsm_x4(uint32_t r[4], uint32_t addr) {
    asm volatile("ldmatrix.sync.aligned.m8n8.x4.shared.b16 {%0,%1,%2,%3}, [%4];"
                 : "=r"(r[0]), "=r"(r[1]), "=r"(r[2]), "=r"(r[3]) : "r"(addr));
}
__device__ __forceinline__ void mma16816(float c[4], const uint32_t a[4],
                                         uint32_t b0, uint32_t b1) {
    asm volatile(
        "mma.sync.aligned.m16n8k16.row.col.f32.f16.f16.f32 "
        "{%0,%1,%2,%3}, {%4,%5,%6,%7}, {%8,%9}, {%0,%1,%2,%3};"
        : "+f"(c[0]), "+f"(c[1]), "+f"(c[2]), "+f"(c[3])
        : "r"(a[0]), "r"(a[1]), "r"(a[2]), "r"(a[3]), "r"(b0), "r"(b1));
}
__device__ __forceinline__ void cp16(uint32_t dst, const void* src) {
    asm volatile("cp.async.cg.shared.global [%0], [%1], 16;"
                 :: "r"(dst), "l"(src));
}
#define CP_COMMIT() asm volatile("cp.async.commit_group;" ::: "memory")
#define CP_WAIT2()  asm volatile("cp.async.wait_group 2;" ::: "memory")
#define CP_WAIT1()  asm volatile("cp.async.wait_group 1;" ::: "memory")
#define CP_WAIT0()  asm volatile("cp.async.wait_group 0;" ::: "memory")

// =================== prep: x -> fp16; W -> transposed fp16 ===================
// blocks [0,2500): x convert; [2500,3012): W cols
__global__ void prep_kernel(const float* __restrict__ x,
                            const float* __restrict__ W) {
    const int bid = blockIdx.x;
    if (bid < 2500) {
        size_t i = (size_t)bid * 512 + threadIdx.x * 2;   // float4 index (2/thread)
        const float4* xp = (const float4*)x;
#pragma unroll
        for (int q = 0; q < 2; ++q) {
            float4 v = xp[i + q];
            __half2 p0 = __floats2half2_rn(v.x, v.y);
            __half2 p1 = __floats2half2_rn(v.z, v.w);
            uint2 pk;
            pk.x = *(uint32_t*)&p0; pk.y = *(uint32_t*)&p1;
            ((uint2*)g_x16)[i + q] = pk;
        }
    } else {
        int n = bid - 2500;
        for (int k = threadIdx.x; k < DD; k += 256) {
            float v = W[(size_t)k * DD + n];
            g_wt[(size_t)n * DD + k] = __float2half_rn(v);
        }
    }
}

// =================== CSR-build kernels (stream 2) ===================
__global__ void init_kernel() {
    int i = blockIdx.x * blockDim.x + threadIdx.x;
    if (i < NN) { g_dinv[i] = 1.0f; g_counts[i] = 0; }
}

__global__ void deg_kernel(const int* __restrict__ eidx,
                           const float* __restrict__ ew) {
    int e = blockIdx.x * blockDim.x + threadIdx.x;
    if (e < EE) {
        int c = eidx[EE + e];
        atomicAdd(&g_dinv[c], ew[e]);
        atomicAdd(&g_counts[c], 1);
    }
}

// scan (warp-shuffle) + dinv finalize, 1 block of 1024
__global__ void scan_kernel() {
    __shared__ int warpsum[32];
    const int CH = (NN + 1023) / 1024;   // 10
    int t = threadIdx.x;
    int lane = t & 31, w = t >> 5;
    int base = t * CH;
    int local[CH];
    int sum = 0;
#pragma unroll
    for (int i = 0; i < CH; ++i) {
        int idx = base + i;
        local[i] = (idx < NN) ? g_counts[idx] : 0;
        sum += local[i];
        if (idx < NN) g_dinv[idx] = rsqrtf(g_dinv[idx]);
    }
    int v = sum;
#pragma unroll
    for (int o = 1; o < 32; o <<= 1) {
        int u = __shfl_up_sync(0xFFFFFFFFu, v, o);
        if (lane >= o) v += u;
    }
    if (lane == 31) warpsum[w] = v;
    __syncthreads();
    if (w == 0) {
        int s = warpsum[lane];
#pragma unroll
        for (int o = 1; o < 32; o <<= 1) {
            int u = __shfl_up_sync(0xFFFFFFFFu, s, o);
            if (lane >= o) s += u;
        }
        warpsum[lane] = s;
    }
    __syncthreads();
    int run = v - sum + (w ? warpsum[w - 1] : 0);
#pragma unroll
    for (int i = 0; i < CH; ++i) {
        int idx = base + i;
        if (idx < NN) {
            g_offsets[idx] = run;
            g_cursor[idx]  = run;
            run += local[i];
        }
    }
    if (t == 1023) g_offsets[NN] = warpsum[31];
}

// fill: resolve (src, norm) per slot (dinv is final here)
__global__ void fill_kernel(const int* __restrict__ eidx,
                            const float* __restrict__ ew) {
    int e = blockIdx.x * blockDim.x + threadIdx.x;
    if (e < EE) {
        int c = eidx[EE + e];
        int r = eidx[e];
        float nrm = g_dinv[r] * ew[e] * g_dinv[c];
        int p = atomicAdd(&g_cursor[c], 1);
        g_esrc[p]  = r;
        g_enorm[p] = nrm;
    }
}

// =================== mma.sync fp16 GEMM: g_h = x16 @ W16 ===================
// CTA tile 128(M) x 128(N), K-chunk 32, 3-stage cp.async pipeline.
// Stage layout (16KB): A 0..8K | B 8K..16K ; 64B rows, SW64.
#define KC 32
#define NCH (DD / KC)            // 16
#define STAGE 16384
#define NSTG 3
#define GEMM_SMEM (NSTG * STAGE) // 49152

__device__ __forceinline__ void gemm_load_stage(uint32_t sb, int stOff, int kc,
                                                int tid, int mBase, int nBase) {
    const int kOff = kc * KC;
#pragma unroll
    for (int it = 0; it < 4; ++it) {
        int vv = tid + it * 256;            // 0..1023
        int row = (vv & 511) >> 2;          // 0..127
        int g   = vv & 3;                   // 16B unit
        const __half* srcp;
        int region;
        size_t srcRow;
        if (vv < 512) {
            int m = mBase + row; if (m > NN - 1) m = NN - 1;
            srcp = g_x16;
            region = 0;
            srcRow = (size_t)m;
        } else {
            srcp = g_wt;
            region = 8192;
            srcRow = (size_t)(nBase + row);
        }
        cp16(sb + stOff + region + SWZ64(row * 64 + g * 16),
             srcp + srcRow * DD + kOff + g * 8);
    }
}

__global__ void __launch_bounds__(256, 2)
gemm_kernel() {
    extern __shared__ char smem[];
    const uint32_t sb = smem_to_u32(smem);
    const int tid  = threadIdx.x;
    const int wid  = tid >> 5;
    const int lane = tid & 31;
    const int wy   = wid >> 2;            // 0..1  (M)
    const int wx   = wid & 3;             // 0..3  (N)
    const int mBase = blockIdx.y * 128;
    const int nBase = blockIdx.x * 128;

    float c[4][4][4];
#pragma unroll
    for (int i = 0; i < 4; ++i)
#pragma unroll
        for (int j = 0; j < 4; ++j)
#pragma unroll
            for (int r = 0; r < 4; ++r) c[i][j][r] = 0.0f;

    const int aRow = wy * 64 + (lane & 15);
    const int aKu  = (lane >> 4);
    const int bRow = wx * 32 + (lane & 7) + ((lane >> 4) & 1) * 8;
    const int bKu  = ((lane >> 3) & 1);

    gemm_load_stage(sb, 0, 0, tid, mBase, nBase);
    CP_COMMIT();
    gemm_load_stage(sb, STAGE, 1, tid, mBase, nBase);
    CP_COMMIT();

    for (int kc = 0; kc < NCH; ++kc) {
        const int stOff = (kc % NSTG) * STAGE;
        if (kc + 2 < NCH) {
            gemm_load_stage(sb, ((kc + 2) % NSTG) * STAGE, kc + 2, tid, mBase, nBase);
            CP_COMMIT();
            CP_WAIT2();
        } else if (kc + 1 < NCH) {
            CP_WAIT1();
        } else {
            CP_WAIT0();
        }
        __syncthreads();

#pragma unroll
        for (int k16 = 0; k16 < 2; ++k16) {
            const int kb = k16 * 2;
            uint32_t a[4][4], b[2][4];
#pragma unroll
            for (int mt = 0; mt < 4; ++mt) {
                int off = SWZ64((aRow + mt * 16) * 64 + (kb + aKu) * 16);
                ldsm_x4(a[mt], sb + stOff + 0 + off);
            }
#pragma unroll
            for (int pr = 0; pr < 2; ++pr) {
                int off = SWZ64((bRow + pr * 16) * 64 + (kb + bKu) * 16);
                ldsm_x4(b[pr], sb + stOff + 8192 + off);
            }
#pragma unroll
            for (int mt = 0; mt < 4; ++mt)
#pragma unroll
                for (int nt = 0; nt < 4; ++nt)
                    mma16816(c[mt][nt], a[mt], b[nt >> 1][(nt & 1) * 2],
                             b[nt >> 1][(nt & 1) * 2 + 1]);
        }
        __syncthreads();
    }

    // epilogue: half2 stores to g_h
    const int erow = mBase + wy * 64 + (lane >> 2);
    const int ecol = nBase + wx * 32 + (lane & 3) * 2;
#pragma unroll
    for (int mt = 0; mt < 4; ++mt) {
#pragma unroll
        for (int nt = 0; nt < 4; ++nt) {
            int r0 = erow + mt * 16;
            int cc = ecol + nt * 8;
            if (r0 < NN) {
                __half2 p = __floats2half2_rn(c[mt][nt][0], c[mt][nt][1]);
                *(__half2*)&g_h[(size_t)r0 * DD + cc] = p;
            }
            if (r0 + 8 < NN) {
                __half2 p = __floats2half2_rn(c[mt][nt][2], c[mt][nt][3]);
                *(__half2*)&g_h[(size_t)(r0 + 8) * DD + cc] = p;
            }
        }
    }
}

// =================== aggregation (fp16 rows, 64 threads/node, unroll 4) ===================
__device__ __forceinline__ void fma_h8(float acc[8], uint4 v, float n) {
    __half2* hp = (__half2*)&v;
#pragma unroll
    for (int q = 0; q < 4; ++q) {
        float2 f = __half22float2(hp[q]);
        acc[q * 2 + 0] += f.x * n;
        acc[q * 2 + 1] += f.y * n;
    }
}

__global__ __launch_bounds__(64)
void agg_kernel(const float* __restrict__ bias,
                float* __restrict__ out) {
    const int i = blockIdx.x;
    const int t = threadIdx.x;          // 0..63, owns 8 columns
    const uint4* hb = (const uint4*)g_h;

    const float di = g_dinv[i];
    float acc[8];
    {
        const float4* bp = (const float4*)(bias + t * 8);
        float4 b0 = bp[0], b1 = bp[1];
        acc[0] = b0.x; acc[1] = b0.y; acc[2] = b0.z; acc[3] = b0.w;
        acc[4] = b1.x; acc[5] = b1.y; acc[6] = b1.z; acc[7] = b1.w;
    }
    // self loop
    fma_h8(acc, hb[(size_t)i * DV8 + t], di * di);

    int k = g_offsets[i];
    const int kend = g_offsets[i + 1];
    for (; k + 3 < kend; k += 4) {
        int r0 = g_esrc[k],     r1 = g_esrc[k + 1];
        int r2 = g_esrc[k + 2], r3 = g_esrc[k + 3];
        float n0 = g_enorm[k],     n1 = g_enorm[k + 1];
        float n2 = g_enorm[k + 2], n3 = g_enorm[k + 3];
        uint4 v0 = hb[(size_t)r0 * DV8 + t];
        uint4 v1 = hb[(size_t)r1 * DV8 + t];
        uint4 v2 = hb[(size_t)r2 * DV8 + t];
        uint4 v3 = hb[(size_t)r3 * DV8 + t];
        fma_h8(acc, v0, n0);
        fma_h8(acc, v1, n1);
        fma_h8(acc, v2, n2);
        fma_h8(acc, v3, n3);
    }
    for (; k < kend; ++k)
        fma_h8(acc, hb[(size_t)g_esrc[k] * DV8 + t], g_enorm[k]);

    float4* op = (float4*)(out + (size_t)i * DD + t * 8);
    op[0] = make_float4(acc[0], acc[1], acc[2], acc[3]);
    op[1] = make_float4(acc[4], acc[5], acc[6], acc[7]);
}

// =================== launcher (fork-join: CSR chain overlaps prep+GEMM) ===================
extern "C" void kernel_launch(void* const* d_in, const int* in_sizes, int n_in,
                              void* d_out, int out_size) {
    const float* x    = (const float*)d_in[0];       // [NN, DD]
    const int*   eidx = (const int*)d_in[1];         // [2, EE] int32
    const float* ea   = (const float*)d_in[2];       // [EE]
    const float* W    = (const float*)d_in[3];       // [DD, DD]
    const float* b    = (const float*)d_in[4];       // [DD]
    float*       out  = (float*)d_out;               // [NN, DD]

    static cudaStream_t s2 = nullptr;
    static cudaEvent_t evFork = nullptr, evJoin = nullptr;
    if (s2 == nullptr) {
        cudaStreamCreateWithFlags(&s2, cudaStreamNonBlocking);
        cudaEventCreateWithFlags(&evFork, cudaEventDisableTiming);
        cudaEventCreateWithFlags(&evJoin, cudaEventDisableTiming);
        cudaFuncSetAttribute(gemm_kernel,
                             cudaFuncAttributeMaxDynamicSharedMemorySize, GEMM_SMEM);
    }

    // fork CSR chain onto s2 immediately
    cudaEventRecord(evFork, 0);
    cudaStreamWaitEvent(s2, evFork, 0);
    init_kernel<<<(NN + 255) / 256, 256, 0, s2>>>();
    deg_kernel<<<(EE + 255) / 256, 256, 0, s2>>>(eidx, ea);
    scan_kernel<<<1, 1024, 0, s2>>>();
    fill_kernel<<<(EE + 255) / 256, 256, 0, s2>>>(eidx, ea);
    cudaEventRecord(evJoin, s2);

    // main stream: prep then GEMM
    prep_kernel<<<3012, 256>>>(x, W);
    dim3 ggrid(DD / 128, (NN + 127) / 128);          // (4, 79)
    gemm_kernel<<<ggrid, 256, GEMM_SMEM>>>();

    // join, then aggregate
    cudaStreamWaitEvent(0, evJoin, 0);
    agg_kernel<<<NN, 64>>>(b, out);
}